// round 1
// baseline (speedup 1.0000x reference)
#include <cuda_runtime.h>
#include <cuda_bf16.h>
#include <math.h>

#define MAXN 100000
#define HDIM 128
#define CDIM 40

// ---------------- device scratch (no allocations allowed) ----------------
__device__ float g_lin[MAXN * HDIM];   // h @ W (pre-aggregation features)
__device__ float g_agg[MAXN * HDIM];   // aggregation accumulator
__device__ float g_h[MAXN * HDIM];     // layer output (post-ReLU)
__device__ float g_norm[MAXN];
__device__ int   g_deg[MAXN];
__device__ float g_Wf[HDIM * CDIM];    // Wp1 @ Wp2
__device__ float g_bf[CDIM];           // bp1 @ Wp2 + bp2
__device__ int   g_is64;               // edge_index dtype flag

// ---------------- edge dtype detection ----------------
// int64 little-endian node ids (< 2^31) => every odd 32-bit word is 0.
__global__ void detect_kernel(const int* __restrict__ ei32, int nHalf) {
    __shared__ int any;
    if (threadIdx.x == 0) any = 0;
    __syncthreads();
    int lim = nHalf < 65536 ? nHalf : 65536;
    int found = 0;
    for (int i = threadIdx.x; i < lim; i += blockDim.x)
        if (ei32[2 * i + 1] != 0) found = 1;
    if (found) atomicOr(&any, 1);
    __syncthreads();
    if (threadIdx.x == 0) g_is64 = (any == 0) ? 1 : 0;
}

__device__ __forceinline__ int load_node(const void* ei, long long i) {
    if (g_is64) return (int)((const long long*)ei)[i];
    return ((const int*)ei)[i];
}

// ---------------- degree / norm ----------------
__global__ void zero_deg_kernel(int M) {
    int i = blockIdx.x * blockDim.x + threadIdx.x;
    if (i < M) g_deg[i] = 0;
}

__global__ void count_deg_kernel(const void* __restrict__ ei, int E) {
    int e = blockIdx.x * blockDim.x + threadIdx.x;
    if (e >= E) return;
    int d = load_node(ei, (long long)E + e);
    atomicAdd(&g_deg[d], 1);
}

__global__ void norm_kernel(int M) {
    int i = blockIdx.x * blockDim.x + threadIdx.x;
    if (i < M) g_norm[i] = rsqrtf((float)g_deg[i] + 1.0f);
}

// ---------------- fold MLP head: Wf = Wp1@Wp2, bf = bp1@Wp2 + bp2 ----------------
__global__ void fuse_w_kernel(const float* __restrict__ Wp1, const float* __restrict__ Wp2) {
    int id = blockIdx.x * blockDim.x + threadIdx.x;
    if (id >= HDIM * CDIM) return;
    int i = id / CDIM, c = id % CDIM;
    float s = 0.f;
    for (int j = 0; j < HDIM; j++)
        s = fmaf(Wp1[i * HDIM + j], Wp2[j * CDIM + c], s);
    g_Wf[id] = s;
}

__global__ void fuse_b_kernel(const float* __restrict__ bp1, const float* __restrict__ Wp2,
                              const float* __restrict__ bp2) {
    int c = threadIdx.x;
    if (c >= CDIM) return;
    float s = bp2[c];
    for (int j = 0; j < HDIM; j++)
        s = fmaf(bp1[j], Wp2[j * CDIM + c], s);
    g_bf[c] = s;
}

// ---------------- GCN GEMM: lin = A @ W ; agg = lin*norm^2 + bias ----------------
// BM=64, full K=128, full N=128. smem: A tile 32KB + W 64KB = 96KB dynamic.
// Thread map: 256 threads = 16 row-groups (TM=4) x 16 col-groups; cols strided by 16
// so W smem reads are conflict-free (16 distinct banks, 2-way broadcast across rg).
__global__ __launch_bounds__(256) void gemm_gcn_kernel(
    const float* __restrict__ A_ext, const float* __restrict__ W,
    const float* __restrict__ bias, int M, int useInternal)
{
    extern __shared__ float sm[];
    float* As = sm;                 // [64][128]
    float* Ws = sm + 64 * HDIM;     // [128][128]
    const float* A = useInternal ? g_h : A_ext;

    int tx = threadIdx.x;
    int rowBase = blockIdx.x * 64;

    const float4* W4 = (const float4*)W;
    float4* Ws4 = (float4*)Ws;
    for (int i = tx; i < HDIM * (HDIM / 4); i += 256) Ws4[i] = W4[i];

    float4* As4 = (float4*)As;
    for (int i = tx; i < 64 * (HDIM / 4); i += 256) {
        int r = i >> 5, c = i & 31;
        int row = rowBase + r;
        float4 v = make_float4(0.f, 0.f, 0.f, 0.f);
        if (row < M) v = *(const float4*)(A + (size_t)row * HDIM + c * 4);
        As4[i] = v;
    }
    __syncthreads();

    int cg = tx & 15;
    int rg = tx >> 4;

    float acc[4][8];
    #pragma unroll
    for (int r = 0; r < 4; r++)
        #pragma unroll
        for (int c = 0; c < 8; c++) acc[r][c] = 0.f;

    const float* Ap = As + (rg * 4) * HDIM;
    const float* Wp = Ws + cg;

    #pragma unroll 8
    for (int k = 0; k < HDIM; k++) {
        float a0 = Ap[k];
        float a1 = Ap[HDIM + k];
        float a2 = Ap[2 * HDIM + k];
        float a3 = Ap[3 * HDIM + k];
        #pragma unroll
        for (int c = 0; c < 8; c++) {
            float b = Wp[k * HDIM + c * 16];
            acc[0][c] = fmaf(a0, b, acc[0][c]);
            acc[1][c] = fmaf(a1, b, acc[1][c]);
            acc[2][c] = fmaf(a2, b, acc[2][c]);
            acc[3][c] = fmaf(a3, b, acc[3][c]);
        }
    }

    #pragma unroll
    for (int r = 0; r < 4; r++) {
        int row = rowBase + rg * 4 + r;
        if (row >= M) break;
        float nr = g_norm[row];
        float n2 = nr * nr;
        float* lp = g_lin + (size_t)row * HDIM;
        float* ap = g_agg + (size_t)row * HDIM;
        #pragma unroll
        for (int c = 0; c < 8; c++) {
            int col = cg + c * 16;
            float v = acc[r][c];
            lp[col] = v;
            ap[col] = fmaf(v, n2, bias[col]);
        }
    }
}

// ---------------- edge scatter: agg[dst] += norm[src]*norm[dst] * lin[src] ----------------
// One warp per edge; lane handles one float4 (32 lanes x 16B = 512B row).
__global__ __launch_bounds__(256) void scatter_kernel(const void* __restrict__ ei, int E)
{
    int gw = (blockIdx.x * 256 + threadIdx.x) >> 5;
    int lane = threadIdx.x & 31;
    if (gw >= E) return;
    int s = load_node(ei, gw);
    int d = load_node(ei, (long long)E + gw);
    float coef = g_norm[s] * g_norm[d];
    float4 v = *(const float4*)(g_lin + (size_t)s * HDIM + lane * 4);
    v.x *= coef; v.y *= coef; v.z *= coef; v.w *= coef;
    float* a = g_agg + (size_t)d * HDIM + lane * 4;
    asm volatile("red.global.add.v4.f32 [%0], {%1, %2, %3, %4};"
                 :: "l"(a), "f"(v.x), "f"(v.y), "f"(v.z), "f"(v.w)
                 : "memory");
}

// ---------------- ReLU: h = max(agg, 0) ----------------
__global__ void relu_kernel(int n4) {
    int i = blockIdx.x * blockDim.x + threadIdx.x;
    if (i >= n4) return;
    float4 v = ((const float4*)g_agg)[i];
    v.x = fmaxf(v.x, 0.f); v.y = fmaxf(v.y, 0.f);
    v.z = fmaxf(v.z, 0.f); v.w = fmaxf(v.w, 0.f);
    ((float4*)g_h)[i] = v;
}

// ---------------- head: logits = h @ Wf + bf ; log_softmax ----------------
// Block = 8 rows (1 warp/row). Wf(20KB)+rows(4KB) in smem.
__global__ __launch_bounds__(256) void final_kernel(float* __restrict__ out, int M)
{
    __shared__ float Wfs[HDIM * CDIM];
    __shared__ float bfs[CDIM];
    __shared__ float rows[8 * HDIM];

    int tx = threadIdx.x;
    for (int i = tx; i < HDIM * CDIM; i += 256) Wfs[i] = g_Wf[i];
    if (tx < CDIM) bfs[tx] = g_bf[tx];

    int rowBase = blockIdx.x * 8;
    for (int i = tx; i < 8 * 32; i += 256) {
        int r = i >> 5, c = i & 31;
        int row = rowBase + r;
        float4 v = make_float4(0.f, 0.f, 0.f, 0.f);
        if (row < M) v = *(const float4*)(g_h + (size_t)row * HDIM + c * 4);
        ((float4*)rows)[i] = v;
    }
    __syncthreads();

    int warp = tx >> 5, lane = tx & 31;
    int row = rowBase + warp;
    if (row >= M) return;

    float s0 = bfs[lane];                          // col = lane (0..31)
    float s1 = (lane < 8) ? bfs[32 + lane] : 0.f;  // col = 32+lane (32..39)
    const float* rp = rows + warp * HDIM;

    #pragma unroll 4
    for (int k = 0; k < HDIM; k++) {
        float a = rp[k];
        s0 = fmaf(a, Wfs[k * CDIM + lane], s0);
        if (lane < 8) s1 = fmaf(a, Wfs[k * CDIM + 32 + lane], s1);
    }

    float m = s0;
    if (lane < 8) m = fmaxf(m, s1);
    #pragma unroll
    for (int o = 16; o > 0; o >>= 1) m = fmaxf(m, __shfl_xor_sync(0xffffffffu, m, o));

    float e = expf(s0 - m) + ((lane < 8) ? expf(s1 - m) : 0.f);
    #pragma unroll
    for (int o = 16; o > 0; o >>= 1) e += __shfl_xor_sync(0xffffffffu, e, o);

    float ls = m + logf(e);
    out[(size_t)row * CDIM + lane] = s0 - ls;
    if (lane < 8) out[(size_t)row * CDIM + 32 + lane] = s1 - ls;
}

// ---------------- launch ----------------
extern "C" void kernel_launch(void* const* d_in, const int* in_sizes, int n_in,
                              void* d_out, int out_size)
{
    const float* x   = (const float*)d_in[0];
    const void*  ei  = d_in[1];
    const float* W1  = (const float*)d_in[2];
    const float* b1  = (const float*)d_in[3];
    const float* W2  = (const float*)d_in[4];
    const float* b2  = (const float*)d_in[5];
    const float* W3  = (const float*)d_in[6];
    const float* b3  = (const float*)d_in[7];
    const float* Wp1 = (const float*)d_in[8];
    const float* bp1 = (const float*)d_in[9];
    const float* Wp2 = (const float*)d_in[10];
    const float* bp2 = (const float*)d_in[11];
    float* out = (float*)d_out;

    int M = in_sizes[0] / HDIM;
    int E = in_sizes[1] / 2;

    const int GEMM_SMEM = (64 * HDIM + HDIM * HDIM) * sizeof(float);  // 96KB
    cudaFuncSetAttribute(gemm_gcn_kernel,
                         cudaFuncAttributeMaxDynamicSharedMemorySize, GEMM_SMEM);

    // dtype detection + degree/norm
    detect_kernel<<<1, 1024>>>((const int*)ei, E);
    zero_deg_kernel<<<(M + 255) / 256, 256>>>(M);
    count_deg_kernel<<<(E + 255) / 256, 256>>>(ei, E);
    norm_kernel<<<(M + 255) / 256, 256>>>(M);

    // fold MLP head weights
    fuse_w_kernel<<<(HDIM * CDIM + 255) / 256, 256>>>(Wp1, Wp2);
    fuse_b_kernel<<<1, 64>>>(bp1, Wp2, bp2);

    int gemmGrid    = (M + 63) / 64;
    int scatterGrid = (E + 7) / 8;
    int n4          = M * HDIM / 4;
    int reluGrid    = (n4 + 255) / 256;

    // layer 1
    gemm_gcn_kernel<<<gemmGrid, 256, GEMM_SMEM>>>(x, W1, b1, M, 0);
    scatter_kernel<<<scatterGrid, 256>>>(ei, E);
    relu_kernel<<<reluGrid, 256>>>(n4);
    // layer 2
    gemm_gcn_kernel<<<gemmGrid, 256, GEMM_SMEM>>>(nullptr, W2, b2, M, 1);
    scatter_kernel<<<scatterGrid, 256>>>(ei, E);
    relu_kernel<<<reluGrid, 256>>>(n4);
    // layer 3
    gemm_gcn_kernel<<<gemmGrid, 256, GEMM_SMEM>>>(nullptr, W3, b3, M, 1);
    scatter_kernel<<<scatterGrid, 256>>>(ei, E);
    relu_kernel<<<reluGrid, 256>>>(n4);

    // head + log_softmax
    final_kernel<<<(M + 7) / 8, 256>>>(out, M);
}

// round 2
// speedup vs baseline: 1.5690x; 1.5690x over previous
#include <cuda_runtime.h>
#include <cuda_bf16.h>
#include <math.h>

#define MAXN 100000
#define MAXE 1600000
#define HDIM 128
#define CDIM 40
#define NBLK ((MAXN + 255) / 256)

// ---------------- device scratch (no allocations allowed) ----------------
__device__ float g_lin[MAXN * HDIM];   // h @ W (pre-aggregation features)
__device__ float g_h[MAXN * HDIM];     // layer output (post-ReLU)
__device__ float g_norm[MAXN];
__device__ int   g_deg[MAXN];
__device__ int   g_rowstart[MAXN + 1]; // CSR row offsets (by dst)
__device__ int   g_cursor[MAXN];
__device__ int   g_bsum[NBLK + 1];
__device__ int2  g_csr[MAXE];          // {src, coef bits} per edge, grouped by dst
__device__ float g_Wf[HDIM * CDIM];    // Wp1 @ Wp2
__device__ float g_bf[CDIM];           // bp1 @ Wp2 + bp2
__device__ int   g_is64;               // edge_index dtype flag

// ---------------- edge dtype detection ----------------
// int64 little-endian node ids (< 2^31) => every odd 32-bit word is 0.
__global__ void detect_kernel(const int* __restrict__ ei32, int nHalf) {
    __shared__ int any;
    if (threadIdx.x == 0) any = 0;
    __syncthreads();
    int lim = nHalf < 65536 ? nHalf : 65536;
    int found = 0;
    for (int i = threadIdx.x; i < lim; i += blockDim.x)
        if (ei32[2 * i + 1] != 0) found = 1;
    if (found) atomicOr(&any, 1);
    __syncthreads();
    if (threadIdx.x == 0) g_is64 = (any == 0) ? 1 : 0;
}

__device__ __forceinline__ int load_node(const void* ei, long long i) {
    if (g_is64) return (int)((const long long*)ei)[i];
    return ((const int*)ei)[i];
}

// ---------------- degree / norm ----------------
__global__ void zero2_kernel(int M) {
    int i = blockIdx.x * blockDim.x + threadIdx.x;
    if (i < M) { g_deg[i] = 0; g_cursor[i] = 0; }
}

__global__ void count_deg_kernel(const void* __restrict__ ei, int E) {
    int e = blockIdx.x * blockDim.x + threadIdx.x;
    if (e >= E) return;
    int d = load_node(ei, (long long)E + e);
    atomicAdd(&g_deg[d], 1);
}

__global__ void norm_kernel(int M) {
    int i = blockIdx.x * blockDim.x + threadIdx.x;
    if (i < M) g_norm[i] = rsqrtf((float)g_deg[i] + 1.0f);
}

// ---------------- prefix sum: g_rowstart = exclusive_scan(g_deg) ----------------
__global__ void bsum_kernel(int M) {
    __shared__ int sd[256];
    int i = blockIdx.x * 256 + threadIdx.x;
    sd[threadIdx.x] = (i < M) ? g_deg[i] : 0;
    __syncthreads();
    for (int o = 128; o > 0; o >>= 1) {
        if (threadIdx.x < o) sd[threadIdx.x] += sd[threadIdx.x + o];
        __syncthreads();
    }
    if (threadIdx.x == 0) g_bsum[blockIdx.x] = sd[0];
}

__global__ void bscan_kernel(int nb) {
    if (threadIdx.x == 0) {
        int run = 0;
        for (int i = 0; i < nb; i++) { int t = g_bsum[i]; g_bsum[i] = run; run += t; }
    }
}

__global__ void rowstart_kernel(int M, int E) {
    __shared__ int sd[256];
    int i = blockIdx.x * 256 + threadIdx.x;
    int v = (i < M) ? g_deg[i] : 0;
    sd[threadIdx.x] = v;
    __syncthreads();
    for (int o = 1; o < 256; o <<= 1) {
        int t = (threadIdx.x >= o) ? sd[threadIdx.x - o] : 0;
        __syncthreads();
        sd[threadIdx.x] += t;
        __syncthreads();
    }
    if (i < M) g_rowstart[i] = g_bsum[blockIdx.x] + sd[threadIdx.x] - v;
    if (i == 0) g_rowstart[M] = E;
}

// ---------------- CSR fill: bucket edges by dst ----------------
__global__ void csr_fill_kernel(const void* __restrict__ ei, int E) {
    int e = blockIdx.x * blockDim.x + threadIdx.x;
    if (e >= E) return;
    int s = load_node(ei, e);
    int d = load_node(ei, (long long)E + e);
    int pos = g_rowstart[d] + atomicAdd(&g_cursor[d], 1);
    float coef = g_norm[s] * g_norm[d];
    g_csr[pos] = make_int2(s, __float_as_int(coef));
}

// ---------------- fold MLP head: Wf = Wp1@Wp2, bf = bp1@Wp2 + bp2 ----------------
__global__ void fuse_w_kernel(const float* __restrict__ Wp1, const float* __restrict__ Wp2) {
    int id = blockIdx.x * blockDim.x + threadIdx.x;
    if (id >= HDIM * CDIM) return;
    int i = id / CDIM, c = id % CDIM;
    float s = 0.f;
    for (int j = 0; j < HDIM; j++)
        s = fmaf(Wp1[i * HDIM + j], Wp2[j * CDIM + c], s);
    g_Wf[id] = s;
}

__global__ void fuse_b_kernel(const float* __restrict__ bp1, const float* __restrict__ Wp2,
                              const float* __restrict__ bp2) {
    int c = threadIdx.x;
    if (c >= CDIM) return;
    float s = bp2[c];
    for (int j = 0; j < HDIM; j++)
        s = fmaf(bp1[j], Wp2[j * CDIM + c], s);
    g_bf[c] = s;
}

// ---------------- GEMM: g_lin = A @ W ----------------
// BM=64, full K=128, full N=128. smem: A tile 32KB + W 64KB = 96KB dynamic.
__global__ __launch_bounds__(256) void gemm_kernel(
    const float* __restrict__ A_ext, const float* __restrict__ W,
    int M, int useInternal)
{
    extern __shared__ float sm[];
    float* As = sm;                 // [64][128]
    float* Ws = sm + 64 * HDIM;     // [128][128]
    const float* A = useInternal ? g_h : A_ext;

    int tx = threadIdx.x;
    int rowBase = blockIdx.x * 64;

    const float4* W4 = (const float4*)W;
    float4* Ws4 = (float4*)Ws;
    for (int i = tx; i < HDIM * (HDIM / 4); i += 256) Ws4[i] = W4[i];

    float4* As4 = (float4*)As;
    for (int i = tx; i < 64 * (HDIM / 4); i += 256) {
        int r = i >> 5, c = i & 31;
        int row = rowBase + r;
        float4 v = make_float4(0.f, 0.f, 0.f, 0.f);
        if (row < M) v = *(const float4*)(A + (size_t)row * HDIM + c * 4);
        As4[i] = v;
    }
    __syncthreads();

    int cg = tx & 15;
    int rg = tx >> 4;

    float acc[4][8];
    #pragma unroll
    for (int r = 0; r < 4; r++)
        #pragma unroll
        for (int c = 0; c < 8; c++) acc[r][c] = 0.f;

    const float* Ap = As + (rg * 4) * HDIM;
    const float* Wp = Ws + cg;

    #pragma unroll 8
    for (int k = 0; k < HDIM; k++) {
        float a0 = Ap[k];
        float a1 = Ap[HDIM + k];
        float a2 = Ap[2 * HDIM + k];
        float a3 = Ap[3 * HDIM + k];
        #pragma unroll
        for (int c = 0; c < 8; c++) {
            float b = Wp[k * HDIM + c * 16];
            acc[0][c] = fmaf(a0, b, acc[0][c]);
            acc[1][c] = fmaf(a1, b, acc[1][c]);
            acc[2][c] = fmaf(a2, b, acc[2][c]);
            acc[3][c] = fmaf(a3, b, acc[3][c]);
        }
    }

    #pragma unroll
    for (int r = 0; r < 4; r++) {
        int row = rowBase + rg * 4 + r;
        if (row >= M) break;
        float* lp = g_lin + (size_t)row * HDIM;
        #pragma unroll
        for (int c = 0; c < 8; c++)
            lp[cg + c * 16] = acc[r][c];
    }
}

// ---------------- gather-aggregate: h = relu(sum coef*lin[src] + lin*n2 + bias) ----------------
// One warp per dst row; lane owns one float4 (32 x 16B = 512B row).
__global__ __launch_bounds__(256) void gather_kernel(const float* __restrict__ bias, int M)
{
    int warp = (blockIdx.x * 256 + threadIdx.x) >> 5;
    int lane = threadIdx.x & 31;
    if (warp >= M) return;
    int row = warp;

    int start = g_rowstart[row];
    int end   = g_rowstart[row + 1];
    float n = g_norm[row];
    float n2 = n * n;

    const float4* linp = (const float4*)g_lin;
    float4 b4 = ((const float4*)bias)[lane];
    float4 self = linp[(size_t)row * 32 + lane];
    float4 acc;
    acc.x = fmaf(self.x, n2, b4.x);
    acc.y = fmaf(self.y, n2, b4.y);
    acc.z = fmaf(self.z, n2, b4.z);
    acc.w = fmaf(self.w, n2, b4.w);

    for (int base = start; base < end; base += 32) {
        int idx = base + lane;
        int2 ec = make_int2(0, 0);
        if (idx < end) ec = g_csr[idx];
        int cnt = min(32, end - base);
        int j = 0;
        for (; j + 1 < cnt; j += 2) {
            int   s0 = __shfl_sync(0xffffffffu, ec.x, j);
            float c0 = __int_as_float(__shfl_sync(0xffffffffu, ec.y, j));
            int   s1 = __shfl_sync(0xffffffffu, ec.x, j + 1);
            float c1 = __int_as_float(__shfl_sync(0xffffffffu, ec.y, j + 1));
            float4 v0 = linp[(size_t)s0 * 32 + lane];
            float4 v1 = linp[(size_t)s1 * 32 + lane];
            acc.x = fmaf(c0, v0.x, acc.x);
            acc.y = fmaf(c0, v0.y, acc.y);
            acc.z = fmaf(c0, v0.z, acc.z);
            acc.w = fmaf(c0, v0.w, acc.w);
            acc.x = fmaf(c1, v1.x, acc.x);
            acc.y = fmaf(c1, v1.y, acc.y);
            acc.z = fmaf(c1, v1.z, acc.z);
            acc.w = fmaf(c1, v1.w, acc.w);
        }
        if (j < cnt) {
            int   s0 = __shfl_sync(0xffffffffu, ec.x, j);
            float c0 = __int_as_float(__shfl_sync(0xffffffffu, ec.y, j));
            float4 v0 = linp[(size_t)s0 * 32 + lane];
            acc.x = fmaf(c0, v0.x, acc.x);
            acc.y = fmaf(c0, v0.y, acc.y);
            acc.z = fmaf(c0, v0.z, acc.z);
            acc.w = fmaf(c0, v0.w, acc.w);
        }
    }

    acc.x = fmaxf(acc.x, 0.f);
    acc.y = fmaxf(acc.y, 0.f);
    acc.z = fmaxf(acc.z, 0.f);
    acc.w = fmaxf(acc.w, 0.f);
    ((float4*)g_h)[(size_t)row * 32 + lane] = acc;
}

// ---------------- head: logits = h @ Wf + bf ; log_softmax ----------------
__global__ __launch_bounds__(256) void final_kernel(float* __restrict__ out, int M)
{
    __shared__ float Wfs[HDIM * CDIM];
    __shared__ float bfs[CDIM];
    __shared__ float rows[8 * HDIM];

    int tx = threadIdx.x;
    for (int i = tx; i < HDIM * CDIM; i += 256) Wfs[i] = g_Wf[i];
    if (tx < CDIM) bfs[tx] = g_bf[tx];

    int rowBase = blockIdx.x * 8;
    for (int i = tx; i < 8 * 32; i += 256) {
        int r = i >> 5, c = i & 31;
        int row = rowBase + r;
        float4 v = make_float4(0.f, 0.f, 0.f, 0.f);
        if (row < M) v = *(const float4*)(g_h + (size_t)row * HDIM + c * 4);
        ((float4*)rows)[i] = v;
    }
    __syncthreads();

    int warp = tx >> 5, lane = tx & 31;
    int row = rowBase + warp;
    if (row >= M) return;

    float s0 = bfs[lane];
    float s1 = (lane < 8) ? bfs[32 + lane] : 0.f;
    const float* rp = rows + warp * HDIM;

    #pragma unroll 4
    for (int k = 0; k < HDIM; k++) {
        float a = rp[k];
        s0 = fmaf(a, Wfs[k * CDIM + lane], s0);
        if (lane < 8) s1 = fmaf(a, Wfs[k * CDIM + 32 + lane], s1);
    }

    float m = s0;
    if (lane < 8) m = fmaxf(m, s1);
    #pragma unroll
    for (int o = 16; o > 0; o >>= 1) m = fmaxf(m, __shfl_xor_sync(0xffffffffu, m, o));

    float e = expf(s0 - m) + ((lane < 8) ? expf(s1 - m) : 0.f);
    #pragma unroll
    for (int o = 16; o > 0; o >>= 1) e += __shfl_xor_sync(0xffffffffu, e, o);

    float ls = m + logf(e);
    out[(size_t)row * CDIM + lane] = s0 - ls;
    if (lane < 8) out[(size_t)row * CDIM + 32 + lane] = s1 - ls;
}

// ---------------- launch ----------------
extern "C" void kernel_launch(void* const* d_in, const int* in_sizes, int n_in,
                              void* d_out, int out_size)
{
    const float* x   = (const float*)d_in[0];
    const void*  ei  = d_in[1];
    const float* W1  = (const float*)d_in[2];
    const float* b1  = (const float*)d_in[3];
    const float* W2  = (const float*)d_in[4];
    const float* b2  = (const float*)d_in[5];
    const float* W3  = (const float*)d_in[6];
    const float* b3  = (const float*)d_in[7];
    const float* Wp1 = (const float*)d_in[8];
    const float* bp1 = (const float*)d_in[9];
    const float* Wp2 = (const float*)d_in[10];
    const float* bp2 = (const float*)d_in[11];
    float* out = (float*)d_out;

    int M = in_sizes[0] / HDIM;
    int E = in_sizes[1] / 2;
    int nb = (M + 255) / 256;

    const int GEMM_SMEM = (64 * HDIM + HDIM * HDIM) * sizeof(float);  // 96KB
    cudaFuncSetAttribute(gemm_kernel,
                         cudaFuncAttributeMaxDynamicSharedMemorySize, GEMM_SMEM);

    // dtype detection + degree/norm + CSR build
    detect_kernel<<<1, 1024>>>((const int*)ei, E);
    zero2_kernel<<<nb, 256>>>(M);
    count_deg_kernel<<<(E + 255) / 256, 256>>>(ei, E);
    norm_kernel<<<nb, 256>>>(M);
    bsum_kernel<<<nb, 256>>>(M);
    bscan_kernel<<<1, 32>>>(nb);
    rowstart_kernel<<<nb, 256>>>(M, E);
    csr_fill_kernel<<<(E + 255) / 256, 256>>>(ei, E);

    // fold MLP head weights
    fuse_w_kernel<<<(HDIM * CDIM + 255) / 256, 256>>>(Wp1, Wp2);
    fuse_b_kernel<<<1, 64>>>(bp1, Wp2, bp2);

    int gemmGrid   = (M + 63) / 64;
    int gatherGrid = (M + 7) / 8;

    // layer 1
    gemm_kernel<<<gemmGrid, 256, GEMM_SMEM>>>(x, W1, M, 0);
    gather_kernel<<<gatherGrid, 256>>>(b1, M);
    // layer 2
    gemm_kernel<<<gemmGrid, 256, GEMM_SMEM>>>(nullptr, W2, M, 1);
    gather_kernel<<<gatherGrid, 256>>>(b2, M);
    // layer 3
    gemm_kernel<<<gemmGrid, 256, GEMM_SMEM>>>(nullptr, W3, M, 1);
    gather_kernel<<<gatherGrid, 256>>>(b3, M);

    // head + log_softmax
    final_kernel<<<(M + 7) / 8, 256>>>(out, M);
}

// round 4
// speedup vs baseline: 1.9958x; 1.2720x over previous
#include <cuda_runtime.h>
#include <cuda_bf16.h>
#include <math.h>
#include <stdint.h>

#define MAXN 100000
#define MAXE 1600000
#define HDIM 128
#define CDIM 40
#define NBLK ((MAXN + 255) / 256)
#define PAD 136  // halves per smem row (128 + 8 pad -> conflict-free ldmatrix)

// ---------------- device scratch ----------------
__device__ float g_lin[MAXN * HDIM];
__device__ float g_h[MAXN * HDIM];
__device__ float g_norm[MAXN];
__device__ int   g_deg[MAXN];
__device__ int   g_rowstart[MAXN + 1];
__device__ int   g_cursor[MAXN];
__device__ int   g_bsum[NBLK + 1];
__device__ int2  g_csr[MAXE];
__device__ float g_Wf[HDIM * CDIM];
__device__ float g_bf[CDIM];
__device__ int   g_is64;
__device__ __nv_bfloat16 g_Bhi16[HDIM * HDIM];  // W^T as [n][k] bf16 hi
__device__ __nv_bfloat16 g_Blo16[HDIM * HDIM];  // lo residual

// ---------------- PTX helpers ----------------
__device__ __forceinline__ uint32_t smem_u32(const void* p) {
    uint32_t a;
    asm("{ .reg .u64 t; cvta.to.shared.u64 t, %1; cvt.u32.u64 %0, t; }" : "=r"(a) : "l"(p));
    return a;
}
__device__ __forceinline__ void ldx4(uint32_t* r, uint32_t addr) {
    asm volatile("ldmatrix.sync.aligned.m8n8.x4.shared.b16 {%0,%1,%2,%3}, [%4];"
                 : "=r"(r[0]), "=r"(r[1]), "=r"(r[2]), "=r"(r[3]) : "r"(addr));
}
__device__ __forceinline__ void mma_bf16(float* d, const uint32_t* a, const uint32_t* b) {
    asm volatile("mma.sync.aligned.m16n8k16.row.col.f32.bf16.bf16.f32 "
                 "{%0,%1,%2,%3}, {%4,%5,%6,%7}, {%8,%9}, {%0,%1,%2,%3};"
                 : "+f"(d[0]), "+f"(d[1]), "+f"(d[2]), "+f"(d[3])
                 : "r"(a[0]), "r"(a[1]), "r"(a[2]), "r"(a[3]), "r"(b[0]), "r"(b[1]));
}

// ---------------- edge dtype detection ----------------
__global__ void detect_kernel(const int* __restrict__ ei32, int nHalf) {
    __shared__ int any;
    if (threadIdx.x == 0) any = 0;
    __syncthreads();
    int lim = nHalf < 65536 ? nHalf : 65536;
    int found = 0;
    for (int i = threadIdx.x; i < lim; i += blockDim.x)
        if (ei32[2 * i + 1] != 0) found = 1;
    if (found) atomicOr(&any, 1);
    __syncthreads();
    if (threadIdx.x == 0) g_is64 = (any == 0) ? 1 : 0;
}

__device__ __forceinline__ int load_node(const void* ei, long long i) {
    if (g_is64) return (int)((const long long*)ei)[i];
    return ((const int*)ei)[i];
}

// ---------------- degree / norm / CSR ----------------
__global__ void zero2_kernel(int M) {
    int i = blockIdx.x * blockDim.x + threadIdx.x;
    if (i < M) { g_deg[i] = 0; g_cursor[i] = 0; }
}
__global__ void count_deg_kernel(const void* __restrict__ ei, int E) {
    int e = blockIdx.x * blockDim.x + threadIdx.x;
    if (e >= E) return;
    atomicAdd(&g_deg[load_node(ei, (long long)E + e)], 1);
}
__global__ void norm_kernel(int M) {
    int i = blockIdx.x * blockDim.x + threadIdx.x;
    if (i < M) g_norm[i] = rsqrtf((float)g_deg[i] + 1.0f);
}
__global__ void bsum_kernel(int M) {
    __shared__ int sd[256];
    int i = blockIdx.x * 256 + threadIdx.x;
    sd[threadIdx.x] = (i < M) ? g_deg[i] : 0;
    __syncthreads();
    for (int o = 128; o > 0; o >>= 1) {
        if (threadIdx.x < o) sd[threadIdx.x] += sd[threadIdx.x + o];
        __syncthreads();
    }
    if (threadIdx.x == 0) g_bsum[blockIdx.x] = sd[0];
}
// parallel exclusive scan over block sums (nb <= 512)
__global__ void bscan_kernel(int nb) {
    __shared__ int sd[512];
    int t = threadIdx.x;
    int v = (t < nb) ? g_bsum[t] : 0;
    sd[t] = v;
    __syncthreads();
    for (int o = 1; o < 512; o <<= 1) {
        int x = (t >= o) ? sd[t - o] : 0;
        __syncthreads();
        sd[t] += x;
        __syncthreads();
    }
    if (t < nb) g_bsum[t] = sd[t] - v;
}
__global__ void rowstart_kernel(int M, int E) {
    __shared__ int sd[256];
    int i = blockIdx.x * 256 + threadIdx.x;
    int v = (i < M) ? g_deg[i] : 0;
    sd[threadIdx.x] = v;
    __syncthreads();
    for (int o = 1; o < 256; o <<= 1) {
        int t = (threadIdx.x >= o) ? sd[threadIdx.x - o] : 0;
        __syncthreads();
        sd[threadIdx.x] += t;
        __syncthreads();
    }
    if (i < M) g_rowstart[i] = g_bsum[blockIdx.x] + sd[threadIdx.x] - v;
    if (i == 0) g_rowstart[M] = E;
}
__global__ void csr_fill_kernel(const void* __restrict__ ei, int E) {
    int e = blockIdx.x * blockDim.x + threadIdx.x;
    if (e >= E) return;
    int s = load_node(ei, e);
    int d = load_node(ei, (long long)E + e);
    int pos = g_rowstart[d] + atomicAdd(&g_cursor[d], 1);
    float coef = g_norm[s] * g_norm[d];
    g_csr[pos] = make_int2(s, __float_as_int(coef));
}

// ---------------- fold MLP head ----------------
__global__ void fuse_w_kernel(const float* __restrict__ Wp1, const float* __restrict__ Wp2) {
    int id = blockIdx.x * blockDim.x + threadIdx.x;
    if (id >= HDIM * CDIM) return;
    int i = id / CDIM, c = id % CDIM;
    float s = 0.f;
    for (int j = 0; j < HDIM; j++)
        s = fmaf(Wp1[i * HDIM + j], Wp2[j * CDIM + c], s);
    g_Wf[id] = s;
}
__global__ void fuse_b_kernel(const float* __restrict__ bp1, const float* __restrict__ Wp2,
                              const float* __restrict__ bp2) {
    int c = threadIdx.x;
    if (c >= CDIM) return;
    float s = bp2[c];
    for (int j = 0; j < HDIM; j++)
        s = fmaf(bp1[j], Wp2[j * CDIM + c], s);
    g_bf[c] = s;
}

// ---------------- W split: B[n][k] = W[k][n] as bf16 hi/lo ----------------
__global__ void w_split_kernel(const float* __restrict__ W) {
    int idx = blockIdx.x * 256 + threadIdx.x;
    if (idx >= HDIM * HDIM) return;
    int n = idx >> 7, k = idx & 127;
    float v = W[k * HDIM + n];
    __nv_bfloat16 h = __float2bfloat16(v);
    __nv_bfloat16 l = __float2bfloat16(v - __bfloat162float(h));
    g_Bhi16[idx] = h;
    g_Blo16[idx] = l;
}

// ---------------- mma.sync GEMM: g_lin = A @ W (fp32 via bf16 hi/lo, 3 terms) ----------------
// CTA: 128x128x128, 256 threads = 8 warps (4x2), warp tile 32x64.
#define GEMM_SMEM (4 * 128 * PAD * 2)

__global__ __launch_bounds__(256) void mma_gemm_kernel(
    const float* __restrict__ A_ext, int M, int useInternal)
{
    extern __shared__ __nv_bfloat16 sm[];
    __nv_bfloat16* sAh = sm;                 // [128][PAD]
    __nv_bfloat16* sAl = sm + 128 * PAD;
    __nv_bfloat16* sBh = sm + 2 * 128 * PAD; // [n][PAD]
    __nv_bfloat16* sBl = sm + 3 * 128 * PAD;
    const float* A = useInternal ? g_h : A_ext;

    int tid = threadIdx.x;
    int rowBase = blockIdx.x * 128;

    // copy pre-split B images
    {
        const uint4* bh = (const uint4*)g_Bhi16;
        const uint4* bl = (const uint4*)g_Blo16;
        for (int i = tid; i < 128 * 16; i += 256) {
            int n = i >> 4, c = i & 15;
            *(uint4*)(sBh + n * PAD + c * 8) = bh[i];
            *(uint4*)(sBl + n * PAD + c * 8) = bl[i];
        }
    }
    // load + split A: each thread covers half a row (64 elems)
    {
        int row = tid >> 1;
        int colBase = (tid & 1) * 64;
        int grow = rowBase + row;
        const float4* Ap = (const float4*)(A + (size_t)grow * HDIM + colBase);
        __nv_bfloat16* dh = sAh + row * PAD + colBase;
        __nv_bfloat16* dl = sAl + row * PAD + colBase;
        #pragma unroll
        for (int j = 0; j < 16; j++) {
            float4 v = make_float4(0.f, 0.f, 0.f, 0.f);
            if (grow < M) v = Ap[j];
            __nv_bfloat16 h0 = __float2bfloat16(v.x);
            __nv_bfloat16 h1 = __float2bfloat16(v.y);
            __nv_bfloat16 h2 = __float2bfloat16(v.z);
            __nv_bfloat16 h3 = __float2bfloat16(v.w);
            dh[j * 4 + 0] = h0; dh[j * 4 + 1] = h1;
            dh[j * 4 + 2] = h2; dh[j * 4 + 3] = h3;
            dl[j * 4 + 0] = __float2bfloat16(v.x - __bfloat162float(h0));
            dl[j * 4 + 1] = __float2bfloat16(v.y - __bfloat162float(h1));
            dl[j * 4 + 2] = __float2bfloat16(v.z - __bfloat162float(h2));
            dl[j * 4 + 3] = __float2bfloat16(v.w - __bfloat162float(h3));
        }
    }
    __syncthreads();

    int lane = tid & 31, wid = tid >> 5;
    int wm = (wid & 3) * 32;   // M offset within tile
    int wn = (wid >> 2) * 64;  // N offset within tile

    uint32_t sbase = smem_u32(sm);
    // ldmatrix lane address offsets
    int a_r = lane & 15;              // A: row within 16
    int a_k = (lane >> 4) * 8;        // A: k chunk
    int b_n = ((lane >> 4) & 1) * 8 + (lane & 7);  // B: n row within 16
    int b_k = ((lane >> 3) & 1) * 8;               // B: k chunk

    uint32_t aAh = sbase + ((wm + a_r) * PAD + a_k) * 2;
    uint32_t aAl = aAh + 128 * PAD * 2;
    uint32_t aBh = sbase + 2 * 128 * PAD * 2 + ((wn + b_n) * PAD + b_k) * 2;
    uint32_t aBl = aBh + 128 * PAD * 2;

    float d[2][8][4];
    #pragma unroll
    for (int mt = 0; mt < 2; mt++)
        #pragma unroll
        for (int nt = 0; nt < 8; nt++)
            #pragma unroll
            for (int r = 0; r < 4; r++) d[mt][nt][r] = 0.f;

    #pragma unroll
    for (int ks = 0; ks < 8; ks++) {
        uint32_t ah[2][4], al[2][4], bh[4][4], bl[4][4];
        uint32_t koff = (uint32_t)(ks * 16 * 2);
        #pragma unroll
        for (int mt = 0; mt < 2; mt++) {
            uint32_t moff = (uint32_t)(mt * 16 * PAD * 2) + koff;
            ldx4(ah[mt], aAh + moff);
            ldx4(al[mt], aAl + moff);
        }
        #pragma unroll
        for (int np = 0; np < 4; np++) {
            uint32_t noff = (uint32_t)(np * 16 * PAD * 2) + koff;
            ldx4(bh[np], aBh + noff);
            ldx4(bl[np], aBl + noff);
        }
        #pragma unroll
        for (int mt = 0; mt < 2; mt++) {
            #pragma unroll
            for (int nt = 0; nt < 8; nt++) {
                uint32_t* ph = &bh[nt >> 1][(nt & 1) * 2];
                uint32_t* pl = &bl[nt >> 1][(nt & 1) * 2];
                mma_bf16(d[mt][nt], ah[mt], ph);
                mma_bf16(d[mt][nt], ah[mt], pl);
                mma_bf16(d[mt][nt], al[mt], ph);
            }
        }
    }

    // epilogue: D[m16n8] lane layout -> g_lin
    int g = lane >> 2, t2 = (lane & 3) * 2;
    #pragma unroll
    for (int mt = 0; mt < 2; mt++) {
        int r0 = rowBase + wm + mt * 16 + g;
        int r1 = r0 + 8;
        #pragma unroll
        for (int nt = 0; nt < 8; nt++) {
            int col = wn + nt * 8 + t2;
            if (r0 < M)
                *(float2*)(g_lin + (size_t)r0 * HDIM + col) = make_float2(d[mt][nt][0], d[mt][nt][1]);
            if (r1 < M)
                *(float2*)(g_lin + (size_t)r1 * HDIM + col) = make_float2(d[mt][nt][2], d[mt][nt][3]);
        }
    }
}

// ---------------- gather-aggregate: h = relu(sum coef*lin[src] + lin*n2 + bias) ----------------
__global__ __launch_bounds__(256) void gather_kernel(const float* __restrict__ bias, int M)
{
    int warp = (blockIdx.x * 256 + threadIdx.x) >> 5;
    int lane = threadIdx.x & 31;
    if (warp >= M) return;
    int row = warp;

    int start = g_rowstart[row];
    int end   = g_rowstart[row + 1];
    float n = g_norm[row];
    float n2 = n * n;

    const float4* linp = (const float4*)g_lin;
    float4 b4 = ((const float4*)bias)[lane];
    float4 self = linp[(size_t)row * 32 + lane];
    float4 acc;
    acc.x = fmaf(self.x, n2, b4.x);
    acc.y = fmaf(self.y, n2, b4.y);
    acc.z = fmaf(self.z, n2, b4.z);
    acc.w = fmaf(self.w, n2, b4.w);

    for (int bse = start; bse < end; bse += 32) {
        int idx = bse + lane;
        int2 ec = make_int2(0, 0);
        if (idx < end) ec = g_csr[idx];
        int cnt = min(32, end - bse);
        int j = 0;
        for (; j + 3 < cnt; j += 4) {
            int   s0 = __shfl_sync(0xffffffffu, ec.x, j);
            int   s1 = __shfl_sync(0xffffffffu, ec.x, j + 1);
            int   s2 = __shfl_sync(0xffffffffu, ec.x, j + 2);
            int   s3 = __shfl_sync(0xffffffffu, ec.x, j + 3);
            float c0 = __int_as_float(__shfl_sync(0xffffffffu, ec.y, j));
            float c1 = __int_as_float(__shfl_sync(0xffffffffu, ec.y, j + 1));
            float c2 = __int_as_float(__shfl_sync(0xffffffffu, ec.y, j + 2));
            float c3 = __int_as_float(__shfl_sync(0xffffffffu, ec.y, j + 3));
            float4 v0 = linp[(size_t)s0 * 32 + lane];
            float4 v1 = linp[(size_t)s1 * 32 + lane];
            float4 v2 = linp[(size_t)s2 * 32 + lane];
            float4 v3 = linp[(size_t)s3 * 32 + lane];
            acc.x = fmaf(c0, v0.x, acc.x); acc.y = fmaf(c0, v0.y, acc.y);
            acc.z = fmaf(c0, v0.z, acc.z); acc.w = fmaf(c0, v0.w, acc.w);
            acc.x = fmaf(c1, v1.x, acc.x); acc.y = fmaf(c1, v1.y, acc.y);
            acc.z = fmaf(c1, v1.z, acc.z); acc.w = fmaf(c1, v1.w, acc.w);
            acc.x = fmaf(c2, v2.x, acc.x); acc.y = fmaf(c2, v2.y, acc.y);
            acc.z = fmaf(c2, v2.z, acc.z); acc.w = fmaf(c2, v2.w, acc.w);
            acc.x = fmaf(c3, v3.x, acc.x); acc.y = fmaf(c3, v3.y, acc.y);
            acc.z = fmaf(c3, v3.z, acc.z); acc.w = fmaf(c3, v3.w, acc.w);
        }
        for (; j < cnt; j++) {
            int   s0 = __shfl_sync(0xffffffffu, ec.x, j);
            float c0 = __int_as_float(__shfl_sync(0xffffffffu, ec.y, j));
            float4 v0 = linp[(size_t)s0 * 32 + lane];
            acc.x = fmaf(c0, v0.x, acc.x); acc.y = fmaf(c0, v0.y, acc.y);
            acc.z = fmaf(c0, v0.z, acc.z); acc.w = fmaf(c0, v0.w, acc.w);
        }
    }

    acc.x = fmaxf(acc.x, 0.f);
    acc.y = fmaxf(acc.y, 0.f);
    acc.z = fmaxf(acc.z, 0.f);
    acc.w = fmaxf(acc.w, 0.f);
    ((float4*)g_h)[(size_t)row * 32 + lane] = acc;
}

// ---------------- head: logits = h @ Wf + bf ; log_softmax ----------------
__global__ __launch_bounds__(256) void final_kernel(float* __restrict__ out, int M)
{
    __shared__ float Wfs[HDIM * CDIM];
    __shared__ float bfs[CDIM];
    __shared__ float rows[8 * HDIM];

    int tx = threadIdx.x;
    for (int i = tx; i < HDIM * CDIM; i += 256) Wfs[i] = g_Wf[i];
    if (tx < CDIM) bfs[tx] = g_bf[tx];

    int rowBase = blockIdx.x * 8;
    for (int i = tx; i < 8 * 32; i += 256) {
        int r = i >> 5, c = i & 31;
        int row = rowBase + r;
        float4 v = make_float4(0.f, 0.f, 0.f, 0.f);
        if (row < M) v = *(const float4*)(g_h + (size_t)row * HDIM + c * 4);
        ((float4*)rows)[i] = v;
    }
    __syncthreads();

    int warp = tx >> 5, lane = tx & 31;
    int row = rowBase + warp;
    if (row >= M) return;

    float s0 = bfs[lane];
    float s1 = (lane < 8) ? bfs[32 + lane] : 0.f;
    const float* rp = rows + warp * HDIM;

    #pragma unroll 4
    for (int k = 0; k < HDIM; k++) {
        float a = rp[k];
        s0 = fmaf(a, Wfs[k * CDIM + lane], s0);
        if (lane < 8) s1 = fmaf(a, Wfs[k * CDIM + 32 + lane], s1);
    }

    float m = s0;
    if (lane < 8) m = fmaxf(m, s1);
    #pragma unroll
    for (int o = 16; o > 0; o >>= 1) m = fmaxf(m, __shfl_xor_sync(0xffffffffu, m, o));

    float e = expf(s0 - m) + ((lane < 8) ? expf(s1 - m) : 0.f);
    #pragma unroll
    for (int o = 16; o > 0; o >>= 1) e += __shfl_xor_sync(0xffffffffu, e, o);

    float ls = m + logf(e);
    out[(size_t)row * CDIM + lane] = s0 - ls;
    if (lane < 8) out[(size_t)row * CDIM + 32 + lane] = s1 - ls;
}

// ---------------- launch ----------------
extern "C" void kernel_launch(void* const* d_in, const int* in_sizes, int n_in,
                              void* d_out, int out_size)
{
    const float* x   = (const float*)d_in[0];
    const void*  ei  = d_in[1];
    const float* W1  = (const float*)d_in[2];
    const float* b1  = (const float*)d_in[3];
    const float* W2  = (const float*)d_in[4];
    const float* b2  = (const float*)d_in[5];
    const float* W3  = (const float*)d_in[6];
    const float* b3  = (const float*)d_in[7];
    const float* Wp1 = (const float*)d_in[8];
    const float* bp1 = (const float*)d_in[9];
    const float* Wp2 = (const float*)d_in[10];
    const float* bp2 = (const float*)d_in[11];
    float* out = (float*)d_out;

    int M = in_sizes[0] / HDIM;
    int E = in_sizes[1] / 2;
    int nb = (M + 255) / 256;

    cudaFuncSetAttribute(mma_gemm_kernel,
                         cudaFuncAttributeMaxDynamicSharedMemorySize, GEMM_SMEM);

    detect_kernel<<<1, 1024>>>((const int*)ei, E);
    zero2_kernel<<<nb, 256>>>(M);
    count_deg_kernel<<<(E + 255) / 256, 256>>>(ei, E);
    norm_kernel<<<nb, 256>>>(M);
    bsum_kernel<<<nb, 256>>>(M);
    bscan_kernel<<<1, 512>>>(nb);
    rowstart_kernel<<<nb, 256>>>(M, E);
    csr_fill_kernel<<<(E + 255) / 256, 256>>>(ei, E);

    fuse_w_kernel<<<(HDIM * CDIM + 255) / 256, 256>>>(Wp1, Wp2);
    fuse_b_kernel<<<1, 64>>>(bp1, Wp2, bp2);

    int gemmGrid   = (M + 127) / 128;
    int gatherGrid = (M + 7) / 8;
    int wsGrid     = (HDIM * HDIM + 255) / 256;

    w_split_kernel<<<wsGrid, 256>>>(W1);
    mma_gemm_kernel<<<gemmGrid, 256, GEMM_SMEM>>>(x, M, 0);
    gather_kernel<<<gatherGrid, 256>>>(b1, M);

    w_split_kernel<<<wsGrid, 256>>>(W2);
    mma_gemm_kernel<<<gemmGrid, 256, GEMM_SMEM>>>(nullptr, M, 1);
    gather_kernel<<<gatherGrid, 256>>>(b2, M);

    w_split_kernel<<<wsGrid, 256>>>(W3);
    mma_gemm_kernel<<<gemmGrid, 256, GEMM_SMEM>>>(nullptr, M, 1);
    gather_kernel<<<gatherGrid, 256>>>(b3, M);

    final_kernel<<<(M + 7) / 8, 256>>>(out, M);
}

// round 5
// speedup vs baseline: 2.6471x; 1.3263x over previous
#include <cuda_runtime.h>
#include <cuda_bf16.h>
#include <cuda_fp16.h>
#include <math.h>
#include <stdint.h>

#define MAXN 100000
#define MAXE 1600000
#define HDIM 128
#define CDIM 40
#define NBLK ((MAXN + 255) / 256)
#define PAD 136  // halves per smem row (128 + 8 pad -> conflict-free ldmatrix)

// ---------------- device scratch ----------------
__device__ __half g_linh[MAXN * HDIM];        // norm[row]*(h@W) in fp16 (gather payload)
__device__ float  g_lin[MAXN * HDIM];         // fp32 logits (head)
__device__ float  g_h[MAXN * HDIM];           // layer output (post-ReLU), fp32
__device__ float  g_norm[MAXN];
__device__ int    g_deg[MAXN];
__device__ int    g_rowstart[MAXN + 1];
__device__ int    g_cursor[MAXN];
__device__ int    g_bsum[NBLK + 1];
__device__ int    g_csrS[MAXE];               // src index per edge, grouped by dst
__device__ float  g_Wf[HDIM * CDIM];
__device__ float  g_bf[CDIM];
__device__ int    g_any;                      // nonzero odd-word flag (int32 edges)
__device__ __nv_bfloat16 g_Bh[4 * HDIM * HDIM];  // W^T bf16 hi images (3 layers + head)
__device__ __nv_bfloat16 g_Bl[4 * HDIM * HDIM];  // lo residuals

// ---------------- PTX helpers ----------------
__device__ __forceinline__ uint32_t smem_u32(const void* p) {
    uint32_t a;
    asm("{ .reg .u64 t; cvta.to.shared.u64 t, %1; cvt.u32.u64 %0, t; }" : "=r"(a) : "l"(p));
    return a;
}
__device__ __forceinline__ void ldx4(uint32_t* r, uint32_t addr) {
    asm volatile("ldmatrix.sync.aligned.m8n8.x4.shared.b16 {%0,%1,%2,%3}, [%4];"
                 : "=r"(r[0]), "=r"(r[1]), "=r"(r[2]), "=r"(r[3]) : "r"(addr));
}
__device__ __forceinline__ void mma_bf16(float* d, const uint32_t* a, const uint32_t* b) {
    asm volatile("mma.sync.aligned.m16n8k16.row.col.f32.bf16.bf16.f32 "
                 "{%0,%1,%2,%3}, {%4,%5,%6,%7}, {%8,%9}, {%0,%1,%2,%3};"
                 : "+f"(d[0]), "+f"(d[1]), "+f"(d[2]), "+f"(d[3])
                 : "r"(a[0]), "r"(a[1]), "r"(a[2]), "r"(a[3]), "r"(b[0]), "r"(b[1]));
}

__device__ __forceinline__ int load_node(const void* ei, long long i, int is64) {
    if (is64) return (int)((const long long*)ei)[i];
    return ((const int*)ei)[i];
}

// ---------------- init: zero deg/cursor + g_any ----------------
__global__ void init_kernel(int M) {
    int i = blockIdx.x * blockDim.x + threadIdx.x;
    if (i < M) { g_deg[i] = 0; g_cursor[i] = 0; }
    if (i == 0) g_any = 0;
}
// int64 little-endian ids < 2^31 => every odd 32-bit word zero
__global__ void detect_kernel(const int* __restrict__ ei32, int nHalf) {
    int found = 0;
    for (int i = blockIdx.x * blockDim.x + threadIdx.x; i < nHalf; i += gridDim.x * blockDim.x)
        if (ei32[2 * i + 1] != 0) found = 1;
    if (found) atomicOr(&g_any, 1);
}
__global__ void count_deg_kernel(const void* __restrict__ ei, int E) {
    int is64 = (g_any == 0);
    int e = blockIdx.x * blockDim.x + threadIdx.x;
    if (e >= E) return;
    atomicAdd(&g_deg[load_node(ei, (long long)E + e, is64)], 1);
}
__global__ void norm_kernel(int M) {
    int i = blockIdx.x * blockDim.x + threadIdx.x;
    if (i < M) g_norm[i] = rsqrtf((float)g_deg[i] + 1.0f);
}
__global__ void bsum_kernel(int M) {
    __shared__ int sd[256];
    int i = blockIdx.x * 256 + threadIdx.x;
    sd[threadIdx.x] = (i < M) ? g_deg[i] : 0;
    __syncthreads();
    for (int o = 128; o > 0; o >>= 1) {
        if (threadIdx.x < o) sd[threadIdx.x] += sd[threadIdx.x + o];
        __syncthreads();
    }
    if (threadIdx.x == 0) g_bsum[blockIdx.x] = sd[0];
}
__global__ void bscan_kernel(int nb) {
    __shared__ int sd[512];
    int t = threadIdx.x;
    int v = (t < nb) ? g_bsum[t] : 0;
    sd[t] = v;
    __syncthreads();
    for (int o = 1; o < 512; o <<= 1) {
        int x = (t >= o) ? sd[t - o] : 0;
        __syncthreads();
        sd[t] += x;
        __syncthreads();
    }
    if (t < nb) g_bsum[t] = sd[t] - v;
}
__global__ void rowstart_kernel(int M, int E) {
    __shared__ int sd[256];
    int i = blockIdx.x * 256 + threadIdx.x;
    int v = (i < M) ? g_deg[i] : 0;
    sd[threadIdx.x] = v;
    __syncthreads();
    for (int o = 1; o < 256; o <<= 1) {
        int t = (threadIdx.x >= o) ? sd[threadIdx.x - o] : 0;
        __syncthreads();
        sd[threadIdx.x] += t;
        __syncthreads();
    }
    if (i < M) g_rowstart[i] = g_bsum[blockIdx.x] + sd[threadIdx.x] - v;
    if (i == 0) g_rowstart[M] = E;
}
__global__ void csr_fill_kernel(const void* __restrict__ ei, int E) {
    int is64 = (g_any == 0);
    int e = blockIdx.x * blockDim.x + threadIdx.x;
    if (e >= E) return;
    int s = load_node(ei, e, is64);
    int d = load_node(ei, (long long)E + e, is64);
    int pos = g_rowstart[d] + atomicAdd(&g_cursor[d], 1);
    g_csrS[pos] = s;
}

// ---------------- fold MLP head: Wf = Wp1@Wp2, bf = bp1@Wp2 + bp2 ----------------
__global__ void fuse_wb_kernel(const float* __restrict__ Wp1, const float* __restrict__ bp1,
                               const float* __restrict__ Wp2, const float* __restrict__ bp2) {
    int id = blockIdx.x * blockDim.x + threadIdx.x;
    if (id < HDIM * CDIM) {
        int i = id / CDIM, c = id % CDIM;
        float s = 0.f;
        for (int j = 0; j < HDIM; j++)
            s = fmaf(Wp1[i * HDIM + j], Wp2[j * CDIM + c], s);
        g_Wf[id] = s;
    } else if (id < HDIM * CDIM + CDIM) {
        int c = id - HDIM * CDIM;
        float s = bp2[c];
        for (int j = 0; j < HDIM; j++)
            s = fmaf(bp1[j], Wp2[j * CDIM + c], s);
        g_bf[c] = s;
    }
}

// ---------------- W splits: B_l[n][k] = W_l[k][n] bf16 hi/lo (3 layers at once) ----------------
__global__ void w_split_all_kernel(const float* __restrict__ W1, const float* __restrict__ W2,
                                   const float* __restrict__ W3) {
    int idx = blockIdx.x * 256 + threadIdx.x;
    if (idx >= 3 * HDIM * HDIM) return;
    int l = idx / (HDIM * HDIM);
    int r = idx - l * HDIM * HDIM;
    int n = r >> 7, k = r & 127;
    const float* W = (l == 0) ? W1 : (l == 1) ? W2 : W3;
    float v = W[k * HDIM + n];
    __nv_bfloat16 h = __float2bfloat16(v);
    g_Bh[idx] = h;
    g_Bl[idx] = __float2bfloat16(v - __bfloat162float(h));
}
// head: slot 3, zero-padded to 128 cols
__global__ void w_split_head_kernel() {
    int idx = blockIdx.x * 256 + threadIdx.x;
    if (idx >= HDIM * HDIM) return;
    int n = idx >> 7, k = idx & 127;
    float v = (n < CDIM) ? g_Wf[k * CDIM + n] : 0.f;
    __nv_bfloat16 h = __float2bfloat16(v);
    g_Bh[3 * HDIM * HDIM + idx] = h;
    g_Bl[3 * HDIM * HDIM + idx] = __float2bfloat16(v - __bfloat162float(h));
}

// ---------------- mma.sync GEMM (fp32 via bf16 hi/lo, 3 terms) ----------------
// CTA: 128x128x128, 256 threads = 8 warps (4x2), warp tile 32x64.
// mode 0: out = norm[row]*(A@W) -> g_linh (fp16).  mode 1: out = A@W -> g_lin (fp32).
#define GEMM_SMEM (4 * 128 * PAD * 2)

__global__ __launch_bounds__(256) void mma_gemm_kernel(
    const float* __restrict__ A_ext, int M, int useInternal, int bsel, int mode)
{
    extern __shared__ __nv_bfloat16 sm[];
    __nv_bfloat16* sAh = sm;                 // [128][PAD]
    __nv_bfloat16* sAl = sm + 128 * PAD;
    __nv_bfloat16* sBh = sm + 2 * 128 * PAD;
    __nv_bfloat16* sBl = sm + 3 * 128 * PAD;
    const float* A = useInternal ? g_h : A_ext;
    const __nv_bfloat16* Bh = g_Bh + bsel * HDIM * HDIM;
    const __nv_bfloat16* Bl = g_Bl + bsel * HDIM * HDIM;

    int tid = threadIdx.x;
    int rowBase = blockIdx.x * 128;

    {
        const uint4* bh = (const uint4*)Bh;
        const uint4* bl = (const uint4*)Bl;
        for (int i = tid; i < 128 * 16; i += 256) {
            int n = i >> 4, c = i & 15;
            *(uint4*)(sBh + n * PAD + c * 8) = bh[i];
            *(uint4*)(sBl + n * PAD + c * 8) = bl[i];
        }
    }
    {
        int row = tid >> 1;
        int colBase = (tid & 1) * 64;
        int grow = rowBase + row;
        const float4* Ap = (const float4*)(A + (size_t)grow * HDIM + colBase);
        __nv_bfloat16* dh = sAh + row * PAD + colBase;
        __nv_bfloat16* dl = sAl + row * PAD + colBase;
        #pragma unroll
        for (int j = 0; j < 16; j++) {
            float4 v = make_float4(0.f, 0.f, 0.f, 0.f);
            if (grow < M) v = Ap[j];
            __nv_bfloat16 h0 = __float2bfloat16(v.x);
            __nv_bfloat16 h1 = __float2bfloat16(v.y);
            __nv_bfloat16 h2 = __float2bfloat16(v.z);
            __nv_bfloat16 h3 = __float2bfloat16(v.w);
            dh[j * 4 + 0] = h0; dh[j * 4 + 1] = h1;
            dh[j * 4 + 2] = h2; dh[j * 4 + 3] = h3;
            dl[j * 4 + 0] = __float2bfloat16(v.x - __bfloat162float(h0));
            dl[j * 4 + 1] = __float2bfloat16(v.y - __bfloat162float(h1));
            dl[j * 4 + 2] = __float2bfloat16(v.z - __bfloat162float(h2));
            dl[j * 4 + 3] = __float2bfloat16(v.w - __bfloat162float(h3));
        }
    }
    __syncthreads();

    int lane = tid & 31, wid = tid >> 5;
    int wm = (wid & 3) * 32;
    int wn = (wid >> 2) * 64;

    uint32_t sbase = smem_u32(sm);
    int a_r = lane & 15;
    int a_k = (lane >> 4) * 8;
    int b_n = ((lane >> 4) & 1) * 8 + (lane & 7);
    int b_k = ((lane >> 3) & 1) * 8;

    uint32_t aAh = sbase + ((wm + a_r) * PAD + a_k) * 2;
    uint32_t aAl = aAh + 128 * PAD * 2;
    uint32_t aBh = sbase + 2 * 128 * PAD * 2 + ((wn + b_n) * PAD + b_k) * 2;
    uint32_t aBl = aBh + 128 * PAD * 2;

    float d[2][8][4];
    #pragma unroll
    for (int mt = 0; mt < 2; mt++)
        #pragma unroll
        for (int nt = 0; nt < 8; nt++)
            #pragma unroll
            for (int r = 0; r < 4; r++) d[mt][nt][r] = 0.f;

    #pragma unroll
    for (int ks = 0; ks < 8; ks++) {
        uint32_t ah[2][4], al[2][4], bh[4][4], bl[4][4];
        uint32_t koff = (uint32_t)(ks * 16 * 2);
        #pragma unroll
        for (int mt = 0; mt < 2; mt++) {
            uint32_t moff = (uint32_t)(mt * 16 * PAD * 2) + koff;
            ldx4(ah[mt], aAh + moff);
            ldx4(al[mt], aAl + moff);
        }
        #pragma unroll
        for (int np = 0; np < 4; np++) {
            uint32_t noff = (uint32_t)(np * 16 * PAD * 2) + koff;
            ldx4(bh[np], aBh + noff);
            ldx4(bl[np], aBl + noff);
        }
        #pragma unroll
        for (int mt = 0; mt < 2; mt++) {
            #pragma unroll
            for (int nt = 0; nt < 8; nt++) {
                uint32_t* ph = &bh[nt >> 1][(nt & 1) * 2];
                uint32_t* pl = &bl[nt >> 1][(nt & 1) * 2];
                mma_bf16(d[mt][nt], ah[mt], ph);
                mma_bf16(d[mt][nt], ah[mt], pl);
                mma_bf16(d[mt][nt], al[mt], ph);
            }
        }
    }

    int g = lane >> 2, t2 = (lane & 3) * 2;
    #pragma unroll
    for (int mt = 0; mt < 2; mt++) {
        int r0 = rowBase + wm + mt * 16 + g;
        int r1 = r0 + 8;
        if (mode == 0) {
            float n0 = (r0 < M) ? g_norm[r0] : 0.f;
            float n1 = (r1 < M) ? g_norm[r1] : 0.f;
            #pragma unroll
            for (int nt = 0; nt < 8; nt++) {
                int col = wn + nt * 8 + t2;
                if (r0 < M) {
                    __half2 hv = __floats2half2_rn(d[mt][nt][0] * n0, d[mt][nt][1] * n0);
                    *(__half2*)&g_linh[(size_t)r0 * HDIM + col] = hv;
                }
                if (r1 < M) {
                    __half2 hv = __floats2half2_rn(d[mt][nt][2] * n1, d[mt][nt][3] * n1);
                    *(__half2*)&g_linh[(size_t)r1 * HDIM + col] = hv;
                }
            }
        } else {
            #pragma unroll
            for (int nt = 0; nt < 8; nt++) {
                int col = wn + nt * 8 + t2;
                if (r0 < M)
                    *(float2*)(g_lin + (size_t)r0 * HDIM + col) = make_float2(d[mt][nt][0], d[mt][nt][1]);
                if (r1 < M)
                    *(float2*)(g_lin + (size_t)r1 * HDIM + col) = make_float2(d[mt][nt][2], d[mt][nt][3]);
            }
        }
    }
}

// ---------------- gather: h = relu(norm[dst]*(sum linh[src] + linh[dst]) + bias) ----------------
// One warp per dst row; lane owns 4 features (8B fp16).
__global__ __launch_bounds__(256) void gather_kernel(const float* __restrict__ bias, int M)
{
    int warp = (blockIdx.x * 256 + threadIdx.x) >> 5;
    int lane = threadIdx.x & 31;
    if (warp >= M) return;
    int row = warp;

    int start = g_rowstart[row];
    int end   = g_rowstart[row + 1];

    const uint2* lp = (const uint2*)g_linh;  // 32 x uint2 per row

    uint2 sv = lp[(size_t)row * 32 + lane];
    float2 a01 = __half22float2(*(__half2*)&sv.x);
    float2 a23 = __half22float2(*(__half2*)&sv.y);
    float4 acc = make_float4(a01.x, a01.y, a23.x, a23.y);

    for (int bse = start; bse < end; bse += 32) {
        int idx = bse + lane;
        int sidx = (idx < end) ? g_csrS[idx] : 0;
        int cnt = min(32, end - bse);
        int j = 0;
        for (; j + 3 < cnt; j += 4) {
            int s0 = __shfl_sync(0xffffffffu, sidx, j);
            int s1 = __shfl_sync(0xffffffffu, sidx, j + 1);
            int s2 = __shfl_sync(0xffffffffu, sidx, j + 2);
            int s3 = __shfl_sync(0xffffffffu, sidx, j + 3);
            uint2 v0 = lp[(size_t)s0 * 32 + lane];
            uint2 v1 = lp[(size_t)s1 * 32 + lane];
            uint2 v2 = lp[(size_t)s2 * 32 + lane];
            uint2 v3 = lp[(size_t)s3 * 32 + lane];
            float2 p, q;
            p = __half22float2(*(__half2*)&v0.x); q = __half22float2(*(__half2*)&v0.y);
            acc.x += p.x; acc.y += p.y; acc.z += q.x; acc.w += q.y;
            p = __half22float2(*(__half2*)&v1.x); q = __half22float2(*(__half2*)&v1.y);
            acc.x += p.x; acc.y += p.y; acc.z += q.x; acc.w += q.y;
            p = __half22float2(*(__half2*)&v2.x); q = __half22float2(*(__half2*)&v2.y);
            acc.x += p.x; acc.y += p.y; acc.z += q.x; acc.w += q.y;
            p = __half22float2(*(__half2*)&v3.x); q = __half22float2(*(__half2*)&v3.y);
            acc.x += p.x; acc.y += p.y; acc.z += q.x; acc.w += q.y;
        }
        for (; j < cnt; j++) {
            int s0 = __shfl_sync(0xffffffffu, sidx, j);
            uint2 v0 = lp[(size_t)s0 * 32 + lane];
            float2 p = __half22float2(*(__half2*)&v0.x);
            float2 q = __half22float2(*(__half2*)&v0.y);
            acc.x += p.x; acc.y += p.y; acc.z += q.x; acc.w += q.y;
        }
    }

    float n = g_norm[row];
    float4 b4 = ((const float4*)bias)[lane];
    float4 h;
    h.x = fmaxf(fmaf(n, acc.x, b4.x), 0.f);
    h.y = fmaxf(fmaf(n, acc.y, b4.y), 0.f);
    h.z = fmaxf(fmaf(n, acc.z, b4.z), 0.f);
    h.w = fmaxf(fmaf(n, acc.w, b4.w), 0.f);
    ((float4*)g_h)[(size_t)row * 32 + lane] = h;
}

// ---------------- log_softmax over logits in g_lin (cols 0..39 of 128-stride rows) ----------------
__global__ __launch_bounds__(256) void logsoftmax_kernel(float* __restrict__ out, int M)
{
    int warp = (blockIdx.x * 256 + threadIdx.x) >> 5;
    int lane = threadIdx.x & 31;
    if (warp >= M) return;
    int row = warp;

    const float* rp = g_lin + (size_t)row * HDIM;
    float l0 = rp[lane] + g_bf[lane];
    float l1 = (lane < 8) ? (rp[32 + lane] + g_bf[32 + lane]) : -1e30f;

    float m = fmaxf(l0, l1);
    #pragma unroll
    for (int o = 16; o > 0; o >>= 1) m = fmaxf(m, __shfl_xor_sync(0xffffffffu, m, o));

    float e = expf(l0 - m) + ((lane < 8) ? expf(l1 - m) : 0.f);
    #pragma unroll
    for (int o = 16; o > 0; o >>= 1) e += __shfl_xor_sync(0xffffffffu, e, o);

    float ls = m + logf(e);
    out[(size_t)row * CDIM + lane] = l0 - ls;
    if (lane < 8) out[(size_t)row * CDIM + 32 + lane] = l1 - ls;
}

// ---------------- launch ----------------
extern "C" void kernel_launch(void* const* d_in, const int* in_sizes, int n_in,
                              void* d_out, int out_size)
{
    const float* x   = (const float*)d_in[0];
    const void*  ei  = d_in[1];
    const float* W1  = (const float*)d_in[2];
    const float* b1  = (const float*)d_in[3];
    const float* W2  = (const float*)d_in[4];
    const float* b2  = (const float*)d_in[5];
    const float* W3  = (const float*)d_in[6];
    const float* b3  = (const float*)d_in[7];
    const float* Wp1 = (const float*)d_in[8];
    const float* bp1 = (const float*)d_in[9];
    const float* Wp2 = (const float*)d_in[10];
    const float* bp2 = (const float*)d_in[11];
    float* out = (float*)d_out;

    int M = in_sizes[0] / HDIM;
    int E = in_sizes[1] / 2;
    int nb = (M + 255) / 256;

    cudaFuncSetAttribute(mma_gemm_kernel,
                         cudaFuncAttributeMaxDynamicSharedMemorySize, GEMM_SMEM);

    init_kernel<<<nb, 256>>>(M);
    detect_kernel<<<128, 256>>>((const int*)ei, E);
    count_deg_kernel<<<(E + 255) / 256, 256>>>(ei, E);
    norm_kernel<<<nb, 256>>>(M);
    bsum_kernel<<<nb, 256>>>(M);
    bscan_kernel<<<1, 512>>>(nb);
    rowstart_kernel<<<nb, 256>>>(M, E);
    csr_fill_kernel<<<(E + 255) / 256, 256>>>(ei, E);

    fuse_wb_kernel<<<(HDIM * CDIM + CDIM + 255) / 256, 256>>>(Wp1, bp1, Wp2, bp2);
    w_split_all_kernel<<<(3 * HDIM * HDIM + 255) / 256, 256>>>(W1, W2, W3);
    w_split_head_kernel<<<(HDIM * HDIM + 255) / 256, 256>>>();

    int gemmGrid   = (M + 127) / 128;
    int gatherGrid = (M + 7) / 8;

    mma_gemm_kernel<<<gemmGrid, 256, GEMM_SMEM>>>(x, M, 0, 0, 0);
    gather_kernel<<<gatherGrid, 256>>>(b1, M);
    mma_gemm_kernel<<<gemmGrid, 256, GEMM_SMEM>>>(nullptr, M, 1, 1, 0);
    gather_kernel<<<gatherGrid, 256>>>(b2, M);
    mma_gemm_kernel<<<gemmGrid, 256, GEMM_SMEM>>>(nullptr, M, 1, 2, 0);
    gather_kernel<<<gatherGrid, 256>>>(b3, M);

    mma_gemm_kernel<<<gemmGrid, 256, GEMM_SMEM>>>(nullptr, M, 1, 3, 1);
    logsoftmax_kernel<<<(M + 7) / 8, 256>>>(out, M);
}